// round 10
// baseline (speedup 1.0000x reference)
#include <cuda_runtime.h>
#include <math.h>

// ---------------------------------------------------------------------------
// CNN-LSTM: emb-gather -> conv1d(K=5,VALID) -> relu -> maxpool(4) -> LSTM -> FC
// B=64 L=4096 VOCAB=20000 E=128 F=64 K=5 P=4 H=128 C=2
//
//   K0: transpose conv_w -> [e][k*64+f]
//   K1: proj[v][k][f] = emb[v] . conv_w[f,:,k]   (20000x320 table, L2-resident)
//   K2: conv+relu+pool via 20 L2-hit gathers per pooled output
//   K3: xg = pooled @ w_ih^T + b_ih + b_hh   (4-row blocked, LDS.128 broadcast)
//   K4: persistent LSTM, 1 CTA/batch, weights in regs+smem, FFMA2,
//       xg double-buffered, h broadcast via LDS.128
// ---------------------------------------------------------------------------

using u64 = unsigned long long;
#define DI __device__ __forceinline__

namespace {
constexpr int B_ = 64, L_ = 4096, E_ = 128, F_ = 64, K_ = 5, H_ = 128;
constexpr int VOCAB_ = 20000;
constexpr int FK_ = K_ * F_;     // 320
constexpr int LP_ = 1023;        // pooled sequence length (4092/4)
constexpr int G_ = 4 * H_;       // 512 gate rows
constexpr int M_ = B_ * LP_;     // 65472 pooled rows
}

// scratch (device globals -- no runtime allocation allowed)
__device__ float g_cwt[E_ * FK_];        // transposed conv weights
__device__ float g_proj[VOCAB_ * FK_];   // 25.6 MB token->conv projection table
__device__ float g_pooled[M_ * F_];      // 16.8 MB pooled features
__device__ float g_xg[M_ * G_];          // 134 MB precomputed gate inputs

// ---- packed f32x2 helpers (Blackwell FFMA2) -------------------------------
DI void fma2(u64 &acc, u64 a, u64 b) {
    asm("fma.rn.f32x2 %0, %1, %2, %0;" : "+l"(acc) : "l"(a), "l"(b));
}
DI u64 pk2(float lo, float hi) {
    u64 r;
    asm("mov.b64 %0, {%1, %2};" : "=l"(r) : "f"(lo), "f"(hi));
    return r;
}
DI float sum2(u64 v) {
    float lo, hi;
    asm("mov.b64 {%0, %1}, %2;" : "=f"(lo), "=f"(hi) : "l"(v));
    return lo + hi;
}

DI float sigf(float x) { return 1.0f / (1.0f + __expf(-x)); }
DI float tanh_s(float x) {
    float ax = fabsf(x);
    float e = __expf(-2.0f * ax);
    float r = (1.0f - e) / (1.0f + e);
    return x < 0.0f ? -r : r;
}

// ---- K0: transpose conv_w [F,E,K] -> g_cwt[e][k*64+f] ---------------------
__global__ void k_wt(const float* __restrict__ cw) {
    int i = blockIdx.x * 256 + threadIdx.x;
    if (i < E_ * FK_) {
        int e = i / FK_, col = i % FK_;
        int k = col >> 6, f = col & 63;
        g_cwt[i] = cw[(f * E_ + e) * K_ + k];
    }
}

// ---- K1: proj table GEMM. CTA = 32 vocab rows staged in smem --------------
__global__ void __launch_bounds__(320) k_proj(const float* __restrict__ emb) {
    __shared__ __align__(16) float es[32 * E_];   // 16 KB
    int c = threadIdx.x;
    u64 w[64];
#pragma unroll
    for (int j = 0; j < 64; j++)
        w[j] = pk2(g_cwt[(2 * j) * FK_ + c], g_cwt[(2 * j + 1) * FK_ + c]);
    int v0 = blockIdx.x * 32;
    const float4* src = (const float4*)(emb + v0 * E_);
    for (int i = threadIdx.x; i < 32 * E_ / 4; i += 320)
        ((float4*)es)[i] = src[i];
    __syncthreads();
#pragma unroll 1
    for (int vi = 0; vi < 32; vi++) {
        const ulonglong2* h4 = (const ulonglong2*)(es + vi * E_);
        u64 a0 = 0ull, a1 = 0ull;
#pragma unroll
        for (int j = 0; j < 32; j++) {
            ulonglong2 h = h4[j];
            fma2(a0, h.x, w[2 * j]);
            fma2(a1, h.y, w[2 * j + 1]);
        }
        g_proj[(v0 + vi) * FK_ + c] = sum2(a0) + sum2(a1);
    }
}

// ---- K2: conv + relu + maxpool. thread = (b, pooled pos p, feature f) -----
__global__ void k_convpool(const int* __restrict__ x, const float* __restrict__ cb) {
    int f = threadIdx.x & 63;
    int p = blockIdx.x * 4 + (threadIdx.x >> 6);
    int b = blockIdx.y;
    if (p >= LP_) return;
    const int* xb = x + b * L_;
    int s0 = p * 4;
    int tok[8];
#pragma unroll
    for (int i = 0; i < 8; i++) tok[i] = __ldg(xb + s0 + i);
    float a0 = 0.f, a1 = 0.f, a2 = 0.f, a3 = 0.f;
#pragma unroll
    for (int k = 0; k < K_; k++) {
        const float* pr = g_proj + k * 64 + f;
        a0 += __ldg(pr + tok[k + 0] * FK_);
        a1 += __ldg(pr + tok[k + 1] * FK_);
        a2 += __ldg(pr + tok[k + 2] * FK_);
        a3 += __ldg(pr + tok[k + 3] * FK_);
    }
    float bias = __ldg(cb + f);
    float m = fmaxf(fmaxf(a0, a1), fmaxf(a2, a3)) + bias;
    g_pooled[(b * LP_ + p) * F_ + f] = fmaxf(m, 0.0f);  // relu(max) == max(relu)
}

// ---- K3: xg = pooled @ w_ih^T + (b_ih + b_hh) ------------------------------
// CTA = 256 threads, 64 pooled rows x 256 gate cols. 4-row register blocking,
// LDS.128 broadcast reads (1 load : 4 FFMA2), 4 independent acc chains.
__global__ void __launch_bounds__(256) k_xgate(const float* __restrict__ wih,
                                               const float* __restrict__ bih,
                                               const float* __restrict__ bhh) {
    __shared__ __align__(16) float ps[64 * F_];   // 16 KB
    int t = threadIdx.x;
    int g = blockIdx.y * 256 + t;
    u64 w[32];
    const u64* wr = (const u64*)(wih + g * F_);
#pragma unroll
    for (int j = 0; j < 32; j++) w[j] = wr[j];
    float bias = __ldg(bih + g) + __ldg(bhh + g);
    int row0 = blockIdx.x * 64;
    const float4* src = (const float4*)(g_pooled + row0 * F_);
#pragma unroll
    for (int i = 0; i < 4; i++) ((float4*)ps)[t + i * 256] = src[t + i * 256];
    __syncthreads();
#pragma unroll 1
    for (int r = 0; r < 64; r += 4) {
        const ulonglong2* p0 = (const ulonglong2*)(ps + (r + 0) * F_);
        const ulonglong2* p1 = (const ulonglong2*)(ps + (r + 1) * F_);
        const ulonglong2* p2 = (const ulonglong2*)(ps + (r + 2) * F_);
        const ulonglong2* p3 = (const ulonglong2*)(ps + (r + 3) * F_);
        u64 a0 = 0ull, a1 = 0ull, a2 = 0ull, a3 = 0ull;
#pragma unroll
        for (int j = 0; j < 16; j++) {
            u64 wl = w[2 * j], wh = w[2 * j + 1];
            ulonglong2 h0 = p0[j], h1 = p1[j], h2 = p2[j], h3 = p3[j];
            fma2(a0, h0.x, wl); fma2(a0, h0.y, wh);
            fma2(a1, h1.x, wl); fma2(a1, h1.y, wh);
            fma2(a2, h2.x, wl); fma2(a2, h2.y, wh);
            fma2(a3, h3.x, wl); fma2(a3, h3.y, wh);
        }
        float* dst = g_xg + (row0 + r) * G_ + g;
        dst[0 * G_] = sum2(a0) + bias;
        dst[1 * G_] = sum2(a1) + bias;
        dst[2 * G_] = sum2(a2) + bias;
        dst[3 * G_] = sum2(a3) + bias;
    }
}

// ---- K4: persistent LSTM. 1 CTA per batch, 256 threads, 2 gate rows each --
// row A = t (i/f gates), row B = t+256 (g/o gates).
// Weights: rowA fully in regs (64 f32x2), rowB 32 f32x2 in regs + 32 in smem.
// xg is double-buffered in registers; h broadcast uses LDS.128.
__global__ void __launch_bounds__(256, 1) k_lstm(const float* __restrict__ whh,
                                                 const float* __restrict__ fcw,
                                                 const float* __restrict__ fcb,
                                                 float* __restrict__ out) {
    extern __shared__ float sm[];
    u64*   wsm = (u64*)sm;           // [32][256] f32x2  -> 64 KB
    float* pre = sm + 16384;         // [512] gate preacts (16B aligned)
    float* hs  = sm + 16896;         // [128] hidden state (16B aligned)
    int t = threadIdx.x;
    int b = blockIdx.x;

    u64 wa[64], wb[32];
    const u64* rA = (const u64*)(whh + t * H_);
    const u64* rB = (const u64*)(whh + (t + 256) * H_);
#pragma unroll
    for (int j = 0; j < 64; j++) wa[j] = rA[j];
#pragma unroll
    for (int j = 0; j < 32; j++) wb[j] = rB[j];
#pragma unroll
    for (int j = 32; j < 64; j++) wsm[(j - 32) * 256 + t] = rB[j];
    if (t < 128) hs[t] = 0.0f;
    float c = 0.0f;
    __syncthreads();

    const float* xgb = g_xg + (size_t)b * (LP_ * G_);
    // prime the xg double buffer
    float xa  = __ldg(xgb + t);
    float xb2 = __ldg(xgb + t + 256);
#pragma unroll 1
    for (int p = 0; p < LP_; p++) {
        // prefetch next step's gate inputs (clamped) -- hides L2/DRAM latency
        int pn = (p + 1 < LP_) ? p + 1 : p;
        float xa_n  = __ldg(xgb + pn * G_ + t);
        float xb_n  = __ldg(xgb + pn * G_ + t + 256);

        const ulonglong2* h4 = (const ulonglong2*)hs;
        u64 aA = 0ull, aB = 0ull;
#pragma unroll
        for (int j = 0; j < 16; j++) {
            ulonglong2 h = h4[j];
            fma2(aA, h.x, wa[2 * j]);     fma2(aB, h.x, wb[2 * j]);
            fma2(aA, h.y, wa[2 * j + 1]); fma2(aB, h.y, wb[2 * j + 1]);
        }
#pragma unroll
        for (int j = 16; j < 32; j++) {
            ulonglong2 h = h4[j];
            fma2(aA, h.x, wa[2 * j]);
            fma2(aA, h.y, wa[2 * j + 1]);
            fma2(aB, h.x, wsm[(2 * j - 32) * 256 + t]);
            fma2(aB, h.y, wsm[(2 * j - 31) * 256 + t]);
        }
        pre[t]       = sum2(aA) + xa;    // rows 0..255   = i,f
        pre[t + 256] = sum2(aB) + xb2;   // rows 256..511 = g,o
        xa = xa_n; xb2 = xb_n;
        __syncthreads();
        if (t < 128) {
            float gi = pre[t], gf = pre[128 + t], gg = pre[256 + t], go = pre[384 + t];
            float ii = sigf(gi), ff = sigf(gf), oo = sigf(go);
            c = ff * c + ii * tanh_s(gg);
            hs[t] = oo * tanh_s(c);
        }
        __syncthreads();
    }

    // final FC: out[b][cc] = h . fc_w[cc] + fc_b[cc]
    if (t < 64) {
        int cc = t >> 5, lane = t & 31;
        float s = 0.0f;
#pragma unroll
        for (int u = 0; u < 4; u++)
            s += hs[lane + u * 32] * __ldg(fcw + cc * H_ + lane + u * 32);
#pragma unroll
        for (int off = 16; off; off >>= 1) s += __shfl_down_sync(0xffffffffu, s, off);
        if (lane == 0) out[b * 2 + cc] = s + __ldg(fcb + cc);
    }
}

// ---------------------------------------------------------------------------
extern "C" void kernel_launch(void* const* d_in, const int* in_sizes, int n_in,
                              void* d_out, int out_size) {
    const int*   x   = (const int*)d_in[0];
    const float* emb = (const float*)d_in[1];
    const float* cw  = (const float*)d_in[2];
    const float* cb  = (const float*)d_in[3];
    const float* wih = (const float*)d_in[4];
    const float* whh = (const float*)d_in[5];
    const float* bih = (const float*)d_in[6];
    const float* bhh = (const float*)d_in[7];
    const float* fcw = (const float*)d_in[8];
    const float* fcb = (const float*)d_in[9];
    float* out = (float*)d_out;

    const int lstm_smem = (16384 + 512 + 128) * 4;  // 68096 B dynamic smem
    cudaFuncSetAttribute(k_lstm, cudaFuncAttributeMaxDynamicSharedMemorySize,
                         lstm_smem);

    k_wt<<<(E_ * FK_ + 255) / 256, 256>>>(cw);
    k_proj<<<VOCAB_ / 32, 320>>>(emb);
    k_convpool<<<dim3((LP_ + 3) / 4, B_), 256>>>(x, cb);
    k_xgate<<<dim3(M_ / 64, 2), 256>>>(wih, bih, bhh);
    k_lstm<<<B_, 256, lstm_smem>>>(whh, fcw, fcb, out);
}

// round 11
// speedup vs baseline: 1.1365x; 1.1365x over previous
#include <cuda_runtime.h>
#include <math.h>

// ---------------------------------------------------------------------------
// CNN-LSTM: emb-gather -> conv1d(K=5,VALID) -> relu -> maxpool(4) -> LSTM -> FC
// B=64 L=4096 VOCAB=20000 E=128 F=64 K=5 P=4 H=128 C=2
//
//   K0: transpose conv_w -> [e][k*64+f]
//   K1: proj[v][k][f] = emb[v] . conv_w[f,:,k]   (20000x320 table, L2-resident)
//   K2: conv+relu+pool via 20 L2-hit gathers per pooled output
//   K3: xg = pooled @ w_ih^T + biases   (4 rows x 2 cols per thread, 1 LDS:4 FFMA2)
//   K4: persistent LSTM, 1 CTA/batch, shuffle-paired gates, ONE barrier/step
// ---------------------------------------------------------------------------

using u64 = unsigned long long;
#define DI __device__ __forceinline__

namespace {
constexpr int B_ = 64, L_ = 4096, E_ = 128, F_ = 64, K_ = 5, H_ = 128;
constexpr int VOCAB_ = 20000;
constexpr int FK_ = K_ * F_;     // 320
constexpr int LP_ = 1023;        // pooled sequence length (4092/4)
constexpr int G_ = 4 * H_;       // 512 gate rows
constexpr int M_ = B_ * LP_;     // 65472 pooled rows
}

// scratch (device globals -- no runtime allocation allowed)
__device__ float g_cwt[E_ * FK_];        // transposed conv weights
__device__ float g_proj[VOCAB_ * FK_];   // 25.6 MB token->conv projection table
__device__ float g_pooled[M_ * F_];      // 16.8 MB pooled features
__device__ float g_xg[M_ * G_];          // 134 MB precomputed gate inputs

// ---- packed f32x2 helpers (Blackwell FFMA2) -------------------------------
DI void fma2(u64 &acc, u64 a, u64 b) {
    asm("fma.rn.f32x2 %0, %1, %2, %0;" : "+l"(acc) : "l"(a), "l"(b));
}
DI u64 pk2(float lo, float hi) {
    u64 r;
    asm("mov.b64 %0, {%1, %2};" : "=l"(r) : "f"(lo), "f"(hi));
    return r;
}
DI float sum2(u64 v) {
    float lo, hi;
    asm("mov.b64 {%0, %1}, %2;" : "=f"(lo), "=f"(hi) : "l"(v));
    return lo + hi;
}

DI float sigf(float x) { return 1.0f / (1.0f + __expf(-x)); }

// ---- K0: transpose conv_w [F,E,K] -> g_cwt[e][k*64+f] ---------------------
__global__ void k_wt(const float* __restrict__ cw) {
    int i = blockIdx.x * 256 + threadIdx.x;
    if (i < E_ * FK_) {
        int e = i / FK_, col = i % FK_;
        int k = col >> 6, f = col & 63;
        g_cwt[i] = cw[(f * E_ + e) * K_ + k];
    }
}

// ---- K1: proj table GEMM. CTA = 32 vocab rows staged in smem --------------
__global__ void __launch_bounds__(320) k_proj(const float* __restrict__ emb) {
    __shared__ __align__(16) float es[32 * E_];   // 16 KB
    int c = threadIdx.x;
    u64 w[64];
#pragma unroll
    for (int j = 0; j < 64; j++)
        w[j] = pk2(g_cwt[(2 * j) * FK_ + c], g_cwt[(2 * j + 1) * FK_ + c]);
    int v0 = blockIdx.x * 32;
    const float4* src = (const float4*)(emb + v0 * E_);
    for (int i = threadIdx.x; i < 32 * E_ / 4; i += 320)
        ((float4*)es)[i] = src[i];
    __syncthreads();
#pragma unroll 1
    for (int vi = 0; vi < 32; vi++) {
        const ulonglong2* h4 = (const ulonglong2*)(es + vi * E_);
        u64 a0 = 0ull, a1 = 0ull;
#pragma unroll
        for (int j = 0; j < 32; j++) {
            ulonglong2 h = h4[j];
            fma2(a0, h.x, w[2 * j]);
            fma2(a1, h.y, w[2 * j + 1]);
        }
        g_proj[(v0 + vi) * FK_ + c] = sum2(a0) + sum2(a1);
    }
}

// ---- K2: conv + relu + maxpool. thread = (b, pooled pos p, feature f) -----
__global__ void k_convpool(const int* __restrict__ x, const float* __restrict__ cb) {
    int f = threadIdx.x & 63;
    int p = blockIdx.x * 4 + (threadIdx.x >> 6);
    int b = blockIdx.y;
    if (p >= LP_) return;
    const int* xb = x + b * L_;
    int s0 = p * 4;
    int tok[8];
#pragma unroll
    for (int i = 0; i < 8; i++) tok[i] = __ldg(xb + s0 + i);
    float a0 = 0.f, a1 = 0.f, a2 = 0.f, a3 = 0.f;
#pragma unroll
    for (int k = 0; k < K_; k++) {
        const float* pr = g_proj + k * 64 + f;
        a0 += __ldg(pr + tok[k + 0] * FK_);
        a1 += __ldg(pr + tok[k + 1] * FK_);
        a2 += __ldg(pr + tok[k + 2] * FK_);
        a3 += __ldg(pr + tok[k + 3] * FK_);
    }
    float bias = __ldg(cb + f);
    float m = fmaxf(fmaxf(a0, a1), fmaxf(a2, a3)) + bias;
    g_pooled[(b * LP_ + p) * F_ + f] = fmaxf(m, 0.0f);  // relu(max) == max(relu)
}

// ---- K3: xg = pooled @ w_ih^T + (b_ih + b_hh) ------------------------------
// CTA = 256 threads covering ALL 512 gate cols (2 cols/thread: t and t+256),
// 64 pooled rows staged in smem. Each LDS.128 broadcast feeds 4 FFMA2.
__global__ void __launch_bounds__(256) k_xgate(const float* __restrict__ wih,
                                               const float* __restrict__ bih,
                                               const float* __restrict__ bhh) {
    __shared__ __align__(16) float ps[64 * F_];   // 16 KB
    int t = threadIdx.x;
    u64 w0[32], w1[32];
    const u64* wr0 = (const u64*)(wih + t * F_);
    const u64* wr1 = (const u64*)(wih + (t + 256) * F_);
#pragma unroll
    for (int j = 0; j < 32; j++) { w0[j] = wr0[j]; w1[j] = wr1[j]; }
    float b0 = __ldg(bih + t) + __ldg(bhh + t);
    float b1 = __ldg(bih + t + 256) + __ldg(bhh + t + 256);
    int row0 = blockIdx.x * 64;
    const float4* src = (const float4*)(g_pooled + row0 * F_);
#pragma unroll
    for (int i = 0; i < 4; i++) ((float4*)ps)[t + i * 256] = src[t + i * 256];
    __syncthreads();
#pragma unroll 1
    for (int r = 0; r < 64; r += 4) {
        const ulonglong2* p0 = (const ulonglong2*)(ps + (r + 0) * F_);
        const ulonglong2* p1 = (const ulonglong2*)(ps + (r + 1) * F_);
        const ulonglong2* p2 = (const ulonglong2*)(ps + (r + 2) * F_);
        const ulonglong2* p3 = (const ulonglong2*)(ps + (r + 3) * F_);
        u64 a0A = 0ull, a1A = 0ull, a2A = 0ull, a3A = 0ull;
        u64 a0B = 0ull, a1B = 0ull, a2B = 0ull, a3B = 0ull;
#pragma unroll
        for (int j = 0; j < 16; j++) {
            u64 wl0 = w0[2 * j], wh0 = w0[2 * j + 1];
            u64 wl1 = w1[2 * j], wh1 = w1[2 * j + 1];
            ulonglong2 h0 = p0[j], h1 = p1[j], h2 = p2[j], h3 = p3[j];
            fma2(a0A, h0.x, wl0); fma2(a0A, h0.y, wh0);
            fma2(a0B, h0.x, wl1); fma2(a0B, h0.y, wh1);
            fma2(a1A, h1.x, wl0); fma2(a1A, h1.y, wh0);
            fma2(a1B, h1.x, wl1); fma2(a1B, h1.y, wh1);
            fma2(a2A, h2.x, wl0); fma2(a2A, h2.y, wh0);
            fma2(a2B, h2.x, wl1); fma2(a2B, h2.y, wh1);
            fma2(a3A, h3.x, wl0); fma2(a3A, h3.y, wh0);
            fma2(a3B, h3.x, wl1); fma2(a3B, h3.y, wh1);
        }
        float* dst = g_xg + (size_t)(row0 + r) * G_ + t;
        dst[0 * G_]       = sum2(a0A) + b0;
        dst[0 * G_ + 256] = sum2(a0B) + b1;
        dst[1 * G_]       = sum2(a1A) + b0;
        dst[1 * G_ + 256] = sum2(a1B) + b1;
        dst[2 * G_]       = sum2(a2A) + b0;
        dst[2 * G_ + 256] = sum2(a2B) + b1;
        dst[3 * G_]       = sum2(a3A) + b0;
        dst[3 * G_ + 256] = sum2(a3B) + b1;
    }
}

// ---- K4: persistent LSTM. 1 CTA/batch, 256 threads, 2 gate rows/thread ----
// Warp w, lane l. Element e = w*16 + (l&15). Lanes 0-15 ("role A") own gate
// rows (i=e, g=256+e) and the cell state c[e]; lanes 16-31 ("role B") own
// rows (f=128+e, o=384+e). f/o activations hop A<-B via __shfl_down(16),
// so each step needs only ONE __syncthreads (publish h).
// Weights: rowA fully in regs (64 u64), rowB 32 u64 regs + 16 ulonglong2 smem.
__global__ void __launch_bounds__(256, 1) k_lstm(const float* __restrict__ whh,
                                                 const float* __restrict__ fcw,
                                                 const float* __restrict__ fcb,
                                                 float* __restrict__ out) {
    extern __shared__ float sm[];
    ulonglong2* wsm = (ulonglong2*)sm;    // [16][256] ulonglong2 -> 64 KB
    float* hs = sm + 16384;               // [128] hidden state (16B aligned)
    int t = threadIdx.x;
    int b = blockIdx.x;
    int l = t & 31;
    bool roleA = (l < 16);
    int e = (t >> 5) * 16 + (l & 15);
    int rowA = roleA ? e : (128 + e);          // i : f
    int rowB = roleA ? (256 + e) : (384 + e);  // g : o

    u64 wa[64], wb[32];
    const u64* rA = (const u64*)(whh + rowA * H_);
    const u64* rB = (const u64*)(whh + rowB * H_);
#pragma unroll
    for (int j = 0; j < 64; j++) wa[j] = rA[j];
#pragma unroll
    for (int j = 0; j < 32; j++) wb[j] = rB[j];
    const ulonglong2* rB2 = (const ulonglong2*)(whh + rowB * H_ + 64);
#pragma unroll
    for (int p2 = 0; p2 < 16; p2++) wsm[p2 * 256 + t] = rB2[p2];
    if (t < 128) hs[t] = 0.0f;
    float c = 0.0f;
    __syncthreads();

    const float* xgb = g_xg + (size_t)b * (LP_ * G_);
    float xa  = __ldg(xgb + rowA);
    float xb2 = __ldg(xgb + rowB);
#pragma unroll 1
    for (int p = 0; p < LP_; p++) {
        // prefetch next step's gate inputs (clamped) -- hides DRAM/L2 latency
        int pn = (p + 1 < LP_) ? p + 1 : p;
        float xa_n = __ldg(xgb + pn * G_ + rowA);
        float xb_n = __ldg(xgb + pn * G_ + rowB);

        const ulonglong2* h4 = (const ulonglong2*)hs;
        u64 aA = 0ull, aB = 0ull;
#pragma unroll
        for (int j = 0; j < 16; j++) {       // h[0:64): both operands in regs
            ulonglong2 h = h4[j];
            fma2(aA, h.x, wa[2 * j]);     fma2(aB, h.x, wb[2 * j]);
            fma2(aA, h.y, wa[2 * j + 1]); fma2(aB, h.y, wb[2 * j + 1]);
        }
#pragma unroll
        for (int j = 16; j < 32; j++) {      // h[64:128): rowB weights from smem
            ulonglong2 h = h4[j];
            ulonglong2 wv = wsm[(j - 16) * 256 + t];
            fma2(aA, h.x, wa[2 * j]);
            fma2(aA, h.y, wa[2 * j + 1]);
            fma2(aB, h.x, wv.x);
            fma2(aB, h.y, wv.y);
        }
        float pA = sum2(aA) + xa;   // i-pre (A) / f-pre (B)
        float pB = sum2(aB) + xb2;  // g-pre (A) / o-pre (B)
        xa = xa_n; xb2 = xb_n;

        float sA = sigf(pA);                       // ii (A) / ff (B)
        float q  = roleA ? (pB + pB) : pB;         // tanh(x)=2*sig(2x)-1
        float sq = sigf(q);
        float vB = roleA ? (2.0f * sq - 1.0f) : sq;  // tg (A) / oo (B)

        float ff = __shfl_down_sync(0xffffffffu, sA, 16);
        float oo = __shfl_down_sync(0xffffffffu, vB, 16);
        if (roleA) {
            c = ff * c + sA * vB;
            float tc = 2.0f * sigf(c + c) - 1.0f;  // tanh(c)
            hs[e] = oo * tc;
        }
        __syncthreads();
    }

    // final FC: out[b][cc] = h . fc_w[cc] + fc_b[cc]
    if (t < 64) {
        int cc = t >> 5, lane = t & 31;
        float s = 0.0f;
#pragma unroll
        for (int u = 0; u < 4; u++)
            s += hs[lane + u * 32] * __ldg(fcw + cc * H_ + lane + u * 32);
#pragma unroll
        for (int off = 16; off; off >>= 1) s += __shfl_down_sync(0xffffffffu, s, off);
        if (lane == 0) out[b * 2 + cc] = s + __ldg(fcb + cc);
    }
}

// ---------------------------------------------------------------------------
extern "C" void kernel_launch(void* const* d_in, const int* in_sizes, int n_in,
                              void* d_out, int out_size) {
    const int*   x   = (const int*)d_in[0];
    const float* emb = (const float*)d_in[1];
    const float* cw  = (const float*)d_in[2];
    const float* cb  = (const float*)d_in[3];
    const float* wih = (const float*)d_in[4];
    const float* whh = (const float*)d_in[5];
    const float* bih = (const float*)d_in[6];
    const float* bhh = (const float*)d_in[7];
    const float* fcw = (const float*)d_in[8];
    const float* fcb = (const float*)d_in[9];
    float* out = (float*)d_out;

    const int lstm_smem = (16384 + 128) * 4;  // 66048 B dynamic smem
    cudaFuncSetAttribute(k_lstm, cudaFuncAttributeMaxDynamicSharedMemorySize,
                         lstm_smem);

    k_wt<<<(E_ * FK_ + 255) / 256, 256>>>(cw);
    k_proj<<<VOCAB_ / 32, 320>>>(emb);
    k_convpool<<<dim3((LP_ + 3) / 4, B_), 256>>>(x, cb);
    k_xgate<<<M_ / 64, 256>>>(wih, bih, bhh);
    k_lstm<<<B_, 256, lstm_smem>>>(whh, fcw, fcb, out);
}